// round 5
// baseline (speedup 1.0000x reference)
#include <cuda_runtime.h>
#include <cuda_pipeline.h>

// Pull_37091337568590, R5: triple-buffered cp.async channel fills (depth-2
// pipeline) + register-resident per-pixel coords.
// x: [8,16,512,512] f32, phi: [8,2,512,512] f32, out: [8,16,512,512] f32.

#define PB 8
#define PC 16
#define PH 512
#define PW 512
#define PHW (PH * PW)

#define TW 64
#define TH 64
#define HR 8
#define SW (TW + 2 * HR)      // 80 floats per tile row
#define SH (TH + 2 * HR)      // 80 rows
#define SSTR 84               // row stride in floats: mult of 4 (16B cp.async)
#define TILE_FLOATS (SH * SSTR)
#define NBUF 3
#define NT 512
#define NPPT 8                // pixels per thread (TH*TW / NT)

__global__ __launch_bounds__(NT)
void pull_tile4_kernel(const float* __restrict__ x,
                       const float* __restrict__ phi,
                       float* __restrict__ out)
{
    extern __shared__ float smem[];

    const int tx0 = blockIdx.x * TW;
    const int ty0 = blockIdx.y * TH;
    const int b   = blockIdx.z;
    const int tid = threadIdx.x;

    const int px = tid & (TW - 1);   // 0..63
    const int py = tid >> 6;         // 0..7

    const float* __restrict__ phiy = phi + (size_t)b * 2 * PHW;
    const float* __restrict__ phix = phiy + PHW;
    const float* __restrict__ xb   = x   + (size_t)b * PC * PHW;
    float* __restrict__ ob         = out + (size_t)b * PC * PHW;

    // ---- fill-lane mapping (no divisions) ----
    const int fr   = tid >> 5;        // 0..15  (row within 16-row pass)
    const int fc4  = tid & 31;        // float4 index, active when < SW/4=20
    const bool factive = (fc4 < SW / 4);
    const int gcol = (tx0 - HR + fc4 * 4) & (PW - 1);  // never crosses wrap in 16B

    // ---- per-pixel coords in registers ----
    unsigned sel[NPPT];
    float    fwy[NPPT], fwx[NPPT];
    #pragma unroll
    for (int i = 0; i < NPPT; i++) {
        int ly = py + i * 8;
        int h  = ty0 + ly;
        int w  = tx0 + px;
        int p  = h * PW + w;

        float cy = __ldg(phiy + p) + (float)h;
        float cx = __ldg(phix + p) + (float)w;
        float y0f = floorf(cy);
        float x0f = floorf(cx);
        fwy[i] = cy - y0f;
        fwx[i] = cx - x0f;

        int y0 = (int)y0f;
        int x0 = (int)x0f;
        int sy = y0 - (ty0 - HR);
        int sx = x0 - (tx0 - HR);

        if ((unsigned)sy < (SH - 1) && (unsigned)sx < (SW - 1)) {
            sel[i] = (unsigned)((sy * SSTR + sx) * 4);      // byte offset in tile
        } else {
            sel[i] = 0x80000000u | ((unsigned)(y0 & (PH - 1)) << 9)
                                 |  (unsigned)(x0 & (PW - 1));
        }
    }

    // ---- fill helper (channel ch into buffer slot) ----
    auto issue_fill = [&](int ch, int slot) {
        const float* xc = xb + ch * PHW;
        float* dst = smem + slot * TILE_FLOATS;
        #pragma unroll
        for (int pass = 0; pass < SH / 16; pass++) {
            int r  = fr + pass * 16;
            int gr = (ty0 - HR + r) & (PH - 1);
            if (factive)
                __pipeline_memcpy_async(dst + r * SSTR + fc4 * 4,
                                        xc + gr * PW + gcol, 16);
        }
        __pipeline_commit();
    };

    // ---- prologue: two fills in flight ----
    issue_fill(0, 0);
    issue_fill(1, 1);

    // ---- per-channel: wait(depth 1), prefetch c+2, blend c ----
    for (int c = 0; c < PC; c++) {
        const float* __restrict__ xc  = xb + c * PHW;
        float* __restrict__ oc        = ob + c * PHW;
        const float* __restrict__ cur = smem + (c % NBUF) * TILE_FLOATS;

        __pipeline_wait_prior(1);   // fill c complete (c+1 may be in flight)
        __syncthreads();            // fills visible; prev blend readers done

        if (c + 2 < PC) issue_fill(c + 2, (c + 2) % NBUF);

        #pragma unroll
        for (int i = 0; i < NPPT; i++) {
            unsigned s = sel[i];
            float wy = fwy[i];
            float wx = fwx[i];

            float v00, v01, v10, v11;
            if (!(s & 0x80000000u)) {
                const float* t = (const float*)((const char*)cur + s);
                v00 = t[0];
                v01 = t[1];
                v10 = t[SSTR];
                v11 = t[SSTR + 1];
            } else {
                int y0 = (int)((s >> 9) & (PH - 1));
                int x0 = (int)(s & (PW - 1));
                int y1 = (y0 + 1) & (PH - 1);
                int x1 = (x0 + 1) & (PW - 1);
                v00 = __ldg(xc + y0 * PW + x0);
                v01 = __ldg(xc + y0 * PW + x1);
                v10 = __ldg(xc + y1 * PW + x0);
                v11 = __ldg(xc + y1 * PW + x1);
            }

            float top = v00 + wx * (v01 - v00);
            float bot = v10 + wx * (v11 - v10);
            float v   = top + wy * (bot - top);

            int ly = py + i * 8;
            oc[(ty0 + ly) * PW + (tx0 + px)] = v;
        }
    }
}

extern "C" void kernel_launch(void* const* d_in, const int* in_sizes, int n_in,
                              void* d_out, int out_size)
{
    const float* x   = (const float*)d_in[0];
    const float* phi = (const float*)d_in[1];
    float* out = (float*)d_out;

    const int smem_bytes = NBUF * TILE_FLOATS * sizeof(float);   // 80640 B
    static int configured = -1;
    if (configured < 0) {
        cudaFuncSetAttribute(pull_tile4_kernel,
                             cudaFuncAttributeMaxDynamicSharedMemorySize,
                             smem_bytes);
        configured = 1;
    }

    dim3 grid(PW / TW, PH / TH, PB);   // 8 x 8 x 8 = 512 blocks
    pull_tile4_kernel<<<grid, NT, smem_bytes>>>(x, phi, out);
}

// round 6
// speedup vs baseline: 1.1915x; 1.1915x over previous
#include <cuda_runtime.h>
#include <cuda_pipeline.h>

// Pull_37091337568590, R6: R4 double-buffered cp.async structure, but
// smaller blocks (256 thr, 64x32 tile) -> 4 independent pipelines/SM.
// x: [8,16,512,512] f32, phi: [8,2,512,512] f32, out: [8,16,512,512] f32.

#define PB 8
#define PC 16
#define PH 512
#define PW 512
#define PHW (PH * PW)

#define TW 64
#define TH 32
#define HR 8
#define SW (TW + 2 * HR)      // 80 floats per tile row
#define SH (TH + 2 * HR)      // 48 rows
#define SSTR 84               // row stride in floats (mult of 4 for 16B cp.async)
#define TILE_FLOATS (SH * SSTR)   // 4032
#define NT 256
#define NPPT 8                // pixels per thread (TH*TW / NT = 2048/256)

__global__ __launch_bounds__(NT)
void pull_tile5_kernel(const float* __restrict__ x,
                       const float* __restrict__ phi,
                       float* __restrict__ out)
{
    extern __shared__ float smem[];
    float* buf0 = smem;
    float* buf1 = smem + TILE_FLOATS;

    const int tx0 = blockIdx.x * TW;
    const int ty0 = blockIdx.y * TH;
    const int b   = blockIdx.z;
    const int tid = threadIdx.x;

    const int px = tid & (TW - 1);   // 0..63
    const int py = tid >> 6;         // 0..3

    const float* __restrict__ phiy = phi + (size_t)b * 2 * PHW;
    const float* __restrict__ phix = phiy + PHW;
    const float* __restrict__ xb   = x   + (size_t)b * PC * PHW;
    float* __restrict__ ob         = out + (size_t)b * PC * PHW;

    // ---- fill-lane mapping: 256 threads, 80 floats (20 float4) per row ----
    const int fr   = tid >> 5;        // 0..7   (row within 8-row pass)
    const int fc4  = tid & 31;        // float4 index, active when < 20
    const bool factive = (fc4 < SW / 4);
    const int gcol = (tx0 - HR + fc4 * 4) & (PW - 1);  // 16B never crosses wrap

    // ---- per-pixel coords in registers ----
    unsigned sel[NPPT];
    float    fwy[NPPT], fwx[NPPT];
    #pragma unroll
    for (int i = 0; i < NPPT; i++) {
        int ly = py + i * 4;          // 0..31
        int h  = ty0 + ly;
        int w  = tx0 + px;
        int p  = h * PW + w;

        float cy = __ldg(phiy + p) + (float)h;
        float cx = __ldg(phix + p) + (float)w;
        float y0f = floorf(cy);
        float x0f = floorf(cx);
        fwy[i] = cy - y0f;
        fwx[i] = cx - x0f;

        int y0 = (int)y0f;
        int x0 = (int)x0f;
        int sy = y0 - (ty0 - HR);
        int sx = x0 - (tx0 - HR);

        if ((unsigned)sy < (SH - 1) && (unsigned)sx < (SW - 1)) {
            sel[i] = (unsigned)((sy * SSTR + sx) * 4);      // byte offset in tile
        } else {
            sel[i] = 0x80000000u | ((unsigned)(y0 & (PH - 1)) << 9)
                                 |  (unsigned)(x0 & (PW - 1));
        }
    }

    // ---- prefetch channel 0 ----
    {
        const float* xc = xb;
        #pragma unroll
        for (int pass = 0; pass < SH / 8; pass++) {
            int r  = fr + pass * 8;
            int gr = (ty0 - HR + r) & (PH - 1);
            if (factive)
                __pipeline_memcpy_async(buf0 + r * SSTR + fc4 * 4,
                                        xc + gr * PW + gcol, 16);
        }
        __pipeline_commit();
    }

    // ---- per-channel: wait, prefetch next, blend ----
    for (int c = 0; c < PC; c++) {
        const float* __restrict__ xc  = xb + c * PHW;
        float* __restrict__ oc        = ob + c * PHW;
        const float* __restrict__ cur = (c & 1) ? buf1 : buf0;

        __pipeline_wait_prior(0);
        __syncthreads();          // fills visible; prev channel's readers done

        if (c + 1 < PC) {
            const float* xn = xc + PHW;
            float* nb = (c & 1) ? buf0 : buf1;
            #pragma unroll
            for (int pass = 0; pass < SH / 8; pass++) {
                int r  = fr + pass * 8;
                int gr = (ty0 - HR + r) & (PH - 1);
                if (factive)
                    __pipeline_memcpy_async(nb + r * SSTR + fc4 * 4,
                                            xn + gr * PW + gcol, 16);
            }
            __pipeline_commit();
        }

        #pragma unroll
        for (int i = 0; i < NPPT; i++) {
            unsigned s = sel[i];
            float wy = fwy[i];
            float wx = fwx[i];

            float v00, v01, v10, v11;
            if (!(s & 0x80000000u)) {
                const float* t = (const float*)((const char*)cur + s);
                v00 = t[0];
                v01 = t[1];
                v10 = t[SSTR];
                v11 = t[SSTR + 1];
            } else {
                int y0 = (int)((s >> 9) & (PH - 1));
                int x0 = (int)(s & (PW - 1));
                int y1 = (y0 + 1) & (PH - 1);
                int x1 = (x0 + 1) & (PW - 1);
                v00 = __ldg(xc + y0 * PW + x0);
                v01 = __ldg(xc + y0 * PW + x1);
                v10 = __ldg(xc + y1 * PW + x0);
                v11 = __ldg(xc + y1 * PW + x1);
            }

            float top = v00 + wx * (v01 - v00);
            float bot = v10 + wx * (v11 - v10);
            float v   = top + wy * (bot - top);

            int ly = py + i * 4;
            oc[(ty0 + ly) * PW + (tx0 + px)] = v;
        }
    }
}

extern "C" void kernel_launch(void* const* d_in, const int* in_sizes, int n_in,
                              void* d_out, int out_size)
{
    const float* x   = (const float*)d_in[0];
    const float* phi = (const float*)d_in[1];
    float* out = (float*)d_out;

    const int smem_bytes = 2 * TILE_FLOATS * sizeof(float);   // 32256 B
    static int configured = -1;
    if (configured < 0) {
        cudaFuncSetAttribute(pull_tile5_kernel,
                             cudaFuncAttributeMaxDynamicSharedMemorySize,
                             smem_bytes);
        configured = 1;
    }

    dim3 grid(PW / TW, PH / TH, PB);   // 8 x 16 x 8 = 1024 blocks
    pull_tile5_kernel<<<grid, NT, smem_bytes>>>(x, phi, out);
}